// round 10
// baseline (speedup 1.0000x reference)
#include <cuda_runtime.h>

// ZapBench volume sampler: quadrilinear (trilinear spatial + linear temporal)
// frames: (T=3, Z=72, Y=512, X=1024) fp32, coords: (N, 4) fp32 [z, y, x, t]
// out: (N, 1) fp32
//
// R10: smem-tiled sampling. Counting-sort points into 4608 SPATIAL bins
// (4x32x64 voxels). Sample kernel: one CTA per bin; stage the bin's halo
// region (5x33x68 floats) for ALL 3 time slices into 134.6KB dynamic smem
// with coalesced float4 streaming, then each point's 16 taps are LDS ops
// instead of random LDG wavefronts (which were the measured 170us floor).

#define T_DIM 3
#define Z_DIM 72
#define Y_DIM 512
#define X_DIM 1024

// Spatial bins: 4 x 32 x 64
#define NZC 18
#define NYC 16
#define NXC 16
#define NBINS (NZC * NYC * NXC)   // 4608

// Halo region per slice (floats): 5 z-planes, 33 y-rows, 68 x (65 used + pad)
#define RZ 5
#define RY 33
#define RXF 68
#define RSLICE (RZ * RY * RXF)    // 11220 floats
#define SMEM_FLOATS (3 * RSLICE)  // 33660 floats = 134640 B
#define R_F4_TOTAL (3 * RZ * RY * (RXF / 4))   // 8415 float4

#define CAP   (1 << 22)           // 4194304 points
#define NCTA  512
#define CHUNK_THREADS 512
#define SAMPLE_THREADS 512

__device__ unsigned int   g_hist2d[NCTA * NBINS];   // [cta][bin]
__device__ unsigned int   g_bintotal[NBINS];
__device__ unsigned int   g_binbase[NBINS];
__device__ unsigned short g_bins[CAP];
__device__ unsigned int   g_sorted_idx[CAP];

__device__ __forceinline__ int compute_bin(float4 c)
{
    // c.x = z_norm, c.y = y_norm, c.z = x_norm (t not part of the key)
    int z0 = min(max((int)(c.x * (float)(Z_DIM - 1)), 0), Z_DIM - 1);
    int y0 = min(max((int)(c.y * (float)(Y_DIM - 1)), 0), Y_DIM - 1);
    int x0 = min(max((int)(c.z * (float)(X_DIM - 1)), 0), X_DIM - 1);
    int zc = z0 >> 2;   // 0..17
    int yc = y0 >> 5;   // 0..15
    int xc = x0 >> 6;   // 0..15
    return (zc * NYC + yc) * NXC + xc;
}

__global__ void __launch_bounds__(CHUNK_THREADS)
hist_kernel(const float4* __restrict__ coords, int n, int chunk)
{
    __shared__ unsigned int s_cnt[NBINS];
    for (int b = threadIdx.x; b < NBINS; b += blockDim.x) s_cnt[b] = 0;
    __syncthreads();

    int start = blockIdx.x * chunk;
    int end   = min(start + chunk, n);

    #pragma unroll 4
    for (int i = start + threadIdx.x; i < end; i += blockDim.x) {
        float4 c = __ldg(&coords[i]);
        int bin = compute_bin(c);
        g_bins[i] = (unsigned short)bin;
        atomicAdd(&s_cnt[bin], 1u);
    }
    __syncthreads();

    unsigned int cta = blockIdx.x;
    for (int b = threadIdx.x; b < NBINS; b += blockDim.x) {
        g_hist2d[cta * NBINS + b] = s_cnt[b];   // coalesced
    }
}

// Scan pass 1: one CTA per bin, exclusive scan of NCTA counts.
__global__ void __launch_bounds__(NCTA)
scan1_kernel()
{
    __shared__ unsigned int buf[2][NCTA];
    int b = blockIdx.x;
    int t = threadIdx.x;

    unsigned int v = g_hist2d[(unsigned int)t * NBINS + b];
    buf[0][t] = v;
    __syncthreads();

    int src = 0;
    for (int d = 1; d < NCTA; d <<= 1) {
        unsigned int x = buf[src][t];
        if (t >= d) x += buf[src][t - d];
        buf[src ^ 1][t] = x;
        __syncthreads();
        src ^= 1;
    }
    unsigned int inclusive = buf[src][t];
    g_hist2d[(unsigned int)t * NBINS + b] = inclusive - v;
    if (t == NCTA - 1) g_bintotal[b] = inclusive;
}

// Scan pass 2: exclusive scan over NBINS (4608) totals; 5 elems per thread.
__global__ void __launch_bounds__(1024)
scan2_kernel()
{
    __shared__ unsigned int buf[2][1024];
    int t = threadIdx.x;

    unsigned int v[5];
    unsigned int s = 0;
    #pragma unroll
    for (int k = 0; k < 5; k++) {
        int b = t * 5 + k;
        v[k] = (b < NBINS) ? g_bintotal[b] : 0u;
        s += v[k];
    }

    buf[0][t] = s;
    __syncthreads();
    int src = 0;
    for (int d = 1; d < 1024; d <<= 1) {
        unsigned int x = buf[src][t];
        if (t >= d) x += buf[src][t - d];
        buf[src ^ 1][t] = x;
        __syncthreads();
        src ^= 1;
    }
    unsigned int run = buf[src][t] - s;   // exclusive base

    #pragma unroll
    for (int k = 0; k < 5; k++) {
        int b = t * 5 + k;
        if (b < NBINS) g_binbase[b] = run;
        run += v[k];
    }
}

// Scatter: indices only, exact positions, no global atomics.
__global__ void __launch_bounds__(CHUNK_THREADS)
scatter_kernel(int n, int chunk)
{
    __shared__ unsigned int s_base[NBINS];
    __shared__ unsigned int s_cnt[NBINS];

    unsigned int cta = blockIdx.x;
    for (int b = threadIdx.x; b < NBINS; b += blockDim.x) {
        s_base[b] = g_binbase[b] + g_hist2d[cta * NBINS + b];
        s_cnt[b]  = 0;
    }
    __syncthreads();

    int start = blockIdx.x * chunk;
    int end   = min(start + chunk, n);

    #pragma unroll 4
    for (int i = start + threadIdx.x; i < end; i += blockDim.x) {
        int bin = g_bins[i];
        unsigned int pos = s_base[bin] + atomicAdd(&s_cnt[bin], 1u);
        g_sorted_idx[pos] = (unsigned int)i;
    }
}

// Trilerp from smem halo region.
__device__ __forceinline__ float trilerp_smem(
    const float* __restrict__ sm, int base, int oz, int oy, int ox,
    float wz, float wy, float wx)
{
    float c000 = sm[base];
    float c001 = sm[base + ox];
    float c010 = sm[base + oy];
    float c011 = sm[base + oy + ox];
    float c100 = sm[base + oz];
    float c101 = sm[base + oz + ox];
    float c110 = sm[base + oz + oy];
    float c111 = sm[base + oz + oy + ox];

    float c00 = fmaf(wx, c001 - c000, c000);
    float c01 = fmaf(wx, c011 - c010, c010);
    float c10 = fmaf(wx, c101 - c100, c100);
    float c11 = fmaf(wx, c111 - c110, c110);
    float c0  = fmaf(wy, c01 - c00, c00);
    float c1  = fmaf(wy, c11 - c10, c10);
    return fmaf(wz, c1 - c0, c0);
}

// One CTA per spatial bin: stage 3-slice halo region into smem, then sample.
__global__ void __launch_bounds__(SAMPLE_THREADS)
sample_tiled_kernel(const float4* __restrict__ coords,
                    const float4* __restrict__ frames4,
                    float*        __restrict__ out)
{
    extern __shared__ float sm[];

    int b = blockIdx.x;
    unsigned int base_j = __ldg(&g_binbase[b]);
    unsigned int cnt    = __ldg(&g_bintotal[b]);
    if (cnt == 0) return;

    int zc = b / (NYC * NXC);
    int rem = b % (NYC * NXC);
    int yc = rem / NXC;
    int xc = rem % NXC;

    // Stage halo region: 3 slices x 5 z-planes x 33 rows x 17 float4.
    float4* sm4 = (float4*)sm;
    for (int f = threadIdx.x; f < R_F4_TOTAL; f += SAMPLE_THREADS) {
        int s  = f / (RZ * RY * 17);
        int r  = f - s * (RZ * RY * 17);
        int z  = r / (RY * 17);
        r     -= z * (RY * 17);
        int y  = r / 17;
        int xq = r - y * 17;

        int gz  = min(zc * 4 + z, Z_DIM - 1);
        int gy  = min(yc * 32 + y, Y_DIM - 1);
        int gx4 = min(xc * 16 + xq, X_DIM / 4 - 1);

        float4 val = __ldg(&frames4[((s * Z_DIM + gz) * Y_DIM + gy) * (X_DIM / 4) + gx4]);
        sm4[f] = val;
    }
    __syncthreads();

    for (unsigned int k = threadIdx.x; k < cnt; k += SAMPLE_THREADS) {
        unsigned int j = base_j + k;
        unsigned int i = __ldg(&g_sorted_idx[j]);
        float4 c = __ldg(&coords[i]);

        float t_abs = c.w * 3.0f;
        int t0 = min(max((int)t_abs, 0), 2);
        int t1 = min(t0 + 1, T_DIM - 1);
        float w = t_abs - (float)t0;

        float sz = c.x * (float)(Z_DIM - 1);
        float sy = c.y * (float)(Y_DIM - 1);
        float sx = c.z * (float)(X_DIM - 1);

        int iz = (int)sz;
        int iy = (int)sy;
        int ix = (int)sx;

        float wz = sz - (float)iz;
        float wy = sy - (float)iy;
        float wx = sx - (float)ix;

        int z0 = max(0, min(iz, Z_DIM - 1));
        int y0 = max(0, min(iy, Y_DIM - 1));
        int x0 = max(0, min(ix, X_DIM - 1));
        int z1 = min(z0 + 1, Z_DIM - 1);
        int y1 = min(y0 + 1, Y_DIM - 1);
        int x1 = min(x0 + 1, X_DIM - 1);

        // Local halo coords (guaranteed in range by bin membership).
        int lz = z0 - zc * 4;
        int ly = y0 - yc * 32;
        int lx = x0 - xc * 64;
        int oz = (z1 - z0) * (RY * RXF);
        int oy = (y1 - y0) * RXF;
        int ox = (x1 - x0);

        int base0 = t0 * RSLICE + (lz * RY + ly) * RXF + lx;
        int base1 = t1 * RSLICE + (lz * RY + ly) * RXF + lx;

        float val0 = trilerp_smem(sm, base0, oz, oy, ox, wz, wy, wx);
        float val1 = trilerp_smem(sm, base1, oz, oy, ox, wz, wy, wx);

        out[i] = fmaf(w, val1 - val0, val0);
    }
}

// Fallback (n > CAP): direct per-point gather.
__device__ __forceinline__ float trilerp_g(
    const float* __restrict__ f, int t,
    int z0, int z1, int y0, int y1, int x0, int x1,
    float wz, float wy, float wx)
{
    const int tb = t * Z_DIM;
    const float* p00 = f + ((long)((tb + z0) * Y_DIM + y0) << 10);
    const float* p01 = f + ((long)((tb + z0) * Y_DIM + y1) << 10);
    const float* p10 = f + ((long)((tb + z1) * Y_DIM + y0) << 10);
    const float* p11 = f + ((long)((tb + z1) * Y_DIM + y1) << 10);
    float c000 = __ldg(p00 + x0), c001 = __ldg(p00 + x1);
    float c010 = __ldg(p01 + x0), c011 = __ldg(p01 + x1);
    float c100 = __ldg(p10 + x0), c101 = __ldg(p10 + x1);
    float c110 = __ldg(p11 + x0), c111 = __ldg(p11 + x1);
    float c00 = fmaf(wx, c001 - c000, c000);
    float c01 = fmaf(wx, c011 - c010, c010);
    float c10 = fmaf(wx, c101 - c100, c100);
    float c11 = fmaf(wx, c111 - c110, c110);
    float c0  = fmaf(wy, c01 - c00, c00);
    float c1  = fmaf(wy, c11 - c10, c10);
    return fmaf(wz, c1 - c0, c0);
}

__global__ void __launch_bounds__(256)
sample_direct_kernel(const float4* __restrict__ coords,
                     const float*  __restrict__ frames,
                     float*        __restrict__ out,
                     int n)
{
    int i = blockIdx.x * blockDim.x + threadIdx.x;
    if (i >= n) return;
    float4 c = __ldg(&coords[i]);

    float t_abs = c.w * 3.0f;
    int t0 = min(max((int)t_abs, 0), 2);
    int t1 = min(t0 + 1, T_DIM - 1);
    float w = t_abs - (float)t0;

    float sz = c.x * (float)(Z_DIM - 1);
    float sy = c.y * (float)(Y_DIM - 1);
    float sx = c.z * (float)(X_DIM - 1);
    int iz = (int)sz, iy = (int)sy, ix = (int)sx;
    float wz = sz - (float)iz, wy = sy - (float)iy, wx = sx - (float)ix;
    int z0 = max(0, min(iz, Z_DIM - 1));
    int y0 = max(0, min(iy, Y_DIM - 1));
    int x0 = max(0, min(ix, X_DIM - 1));
    int z1 = min(z0 + 1, Z_DIM - 1);
    int y1 = min(y0 + 1, Y_DIM - 1);
    int x1 = min(x0 + 1, X_DIM - 1);

    float val0 = trilerp_g(frames, t0, z0, z1, y0, y1, x0, x1, wz, wy, wx);
    float val1 = trilerp_g(frames, t1, z0, z1, y0, y1, x0, x1, wz, wy, wx);
    out[i] = fmaf(w, val1 - val0, val0);
}

extern "C" void kernel_launch(void* const* d_in, const int* in_sizes, int n_in,
                              void* d_out, int out_size)
{
    const float4* coords = (const float4*)d_in[0];
    const float*  frames = (const float*)d_in[1];
    float* out = (float*)d_out;

    int n = in_sizes[0] / 4;   // coords is (N,4) floats

    if (n > CAP) {
        int blocks = (n + 255) / 256;
        sample_direct_kernel<<<blocks, 256>>>(coords, frames, out, n);
        return;
    }

    static const int SMEM_BYTES = SMEM_FLOATS * (int)sizeof(float);
    cudaFuncSetAttribute(sample_tiled_kernel,
                         cudaFuncAttributeMaxDynamicSharedMemorySize, SMEM_BYTES);

    int chunk = (n + NCTA - 1) / NCTA;

    hist_kernel<<<NCTA, CHUNK_THREADS>>>(coords, n, chunk);
    scan1_kernel<<<NBINS, NCTA>>>();
    scan2_kernel<<<1, 1024>>>();
    scatter_kernel<<<NCTA, CHUNK_THREADS>>>(n, chunk);
    sample_tiled_kernel<<<NBINS, SAMPLE_THREADS, SMEM_BYTES>>>(
        coords, (const float4*)frames, out);
}

// round 11
// speedup vs baseline: 2.1199x; 2.1199x over previous
#include <cuda_runtime.h>

// ZapBench volume sampler: quadrilinear (trilinear spatial + linear temporal)
// frames: (T=3, Z=72, Y=512, X=1024) fp32, coords: (N, 4) fp32 [z, y, x, t]
// out: (N, 1) fp32
//
// Pipeline: atomic-free counting sort of point INDICES into 1728 bins
// (t innermost), then a gather kernel with float4-window loads.
// R10 lesson: 134KB smem tiling collapses occupancy (1 CTA/SM) and
// serializes staging -> 2x slower. This is the proven gather design:
// R8 structure + R9 transposed hist2d + NCTA=512.

#define T_DIM 3
#define Z_DIM 72
#define Y_DIM 512
#define X_DIM 1024

#define NBINS (9 * 8 * 8 * 3)   // (z/8, y/64, x/128) spatial, t0 innermost
#define CAP   (1 << 22)         // 4194304 points
#define NCTA  512
#define CHUNK_THREADS 512

__device__ unsigned int   g_hist2d[NCTA * NBINS];   // [cta][bin] (transposed)
__device__ unsigned int   g_bintotal[NBINS];
__device__ unsigned int   g_binbase[NBINS];
__device__ unsigned short g_bins[CAP];
__device__ unsigned int   g_sorted_idx[CAP];

__device__ __forceinline__ int compute_bin(float4 c)
{
    float t_abs = c.w * 3.0f;
    int t0 = min(max((int)t_abs, 0), 2);
    int zc = min(max((int)(c.x * (float)(Z_DIM - 1)), 0), Z_DIM - 1) >> 3;   // 0..8
    int yc = min(max((int)(c.y * (float)(Y_DIM - 1)), 0), Y_DIM - 1) >> 6;   // 0..7
    int xc = min(max((int)(c.z * (float)(X_DIM - 1)), 0), X_DIM - 1) >> 7;   // 0..7
    return (((zc * 8 + yc) * 8 + xc) * 3) + t0;   // t innermost
}

__global__ void __launch_bounds__(CHUNK_THREADS)
hist_kernel(const float4* __restrict__ coords, int n, int chunk)
{
    __shared__ unsigned int s_cnt[NBINS];
    for (int b = threadIdx.x; b < NBINS; b += blockDim.x) s_cnt[b] = 0;
    __syncthreads();

    int start = blockIdx.x * chunk;
    int end   = min(start + chunk, n);

    #pragma unroll 4
    for (int i = start + threadIdx.x; i < end; i += blockDim.x) {
        float4 c = __ldg(&coords[i]);
        int bin = compute_bin(c);
        g_bins[i] = (unsigned short)bin;
        atomicAdd(&s_cnt[bin], 1u);
    }
    __syncthreads();

    // Coalesced: consecutive threads write consecutive bins of this CTA's row.
    unsigned int cta = blockIdx.x;
    for (int b = threadIdx.x; b < NBINS; b += blockDim.x) {
        g_hist2d[cta * NBINS + b] = s_cnt[b];
    }
}

// Scan pass 1: one CTA per bin, exclusive scan of the NCTA counts
// (stride-NBINS; tiny latency-tolerant kernel with 1728-CTA parallelism).
__global__ void __launch_bounds__(NCTA)
scan1_kernel()
{
    __shared__ unsigned int buf[2][NCTA];
    int b = blockIdx.x;
    int t = threadIdx.x;

    unsigned int v = g_hist2d[(unsigned int)t * NBINS + b];
    buf[0][t] = v;
    __syncthreads();

    int src = 0;
    for (int d = 1; d < NCTA; d <<= 1) {
        unsigned int x = buf[src][t];
        if (t >= d) x += buf[src][t - d];
        buf[src ^ 1][t] = x;
        __syncthreads();
        src ^= 1;
    }
    unsigned int inclusive = buf[src][t];
    g_hist2d[(unsigned int)t * NBINS + b] = inclusive - v;
    if (t == NCTA - 1) g_bintotal[b] = inclusive;
}

// Scan pass 2: exclusive scan over NBINS bin totals.
__global__ void __launch_bounds__(1024)
scan2_kernel()
{
    __shared__ unsigned int buf[2][1024];
    int t = threadIdx.x;

    unsigned int h0 = (2 * t     < NBINS) ? g_bintotal[2 * t]     : 0u;
    unsigned int h1 = (2 * t + 1 < NBINS) ? g_bintotal[2 * t + 1] : 0u;
    unsigned int sum = h0 + h1;

    buf[0][t] = sum;
    __syncthreads();
    int src = 0;
    for (int d = 1; d < 1024; d <<= 1) {
        unsigned int v = buf[src][t];
        if (t >= d) v += buf[src][t - d];
        buf[src ^ 1][t] = v;
        __syncthreads();
        src ^= 1;
    }
    unsigned int inclusive = buf[src][t];
    unsigned int base = inclusive - sum;

    if (2 * t     < NBINS) g_binbase[2 * t]     = base;
    if (2 * t + 1 < NBINS) g_binbase[2 * t + 1] = base + h0;
}

// Scatter: indices only, exact precomputed positions, no global atomics.
__global__ void __launch_bounds__(CHUNK_THREADS)
scatter_kernel(int n, int chunk)
{
    __shared__ unsigned int s_base[NBINS];
    __shared__ unsigned int s_cnt[NBINS];

    unsigned int cta = blockIdx.x;
    // Coalesced reads of this CTA's hist2d row.
    for (int b = threadIdx.x; b < NBINS; b += blockDim.x) {
        s_base[b] = g_binbase[b] + g_hist2d[cta * NBINS + b];
        s_cnt[b]  = 0;
    }
    __syncthreads();

    int start = blockIdx.x * chunk;
    int end   = min(start + chunk, n);

    #pragma unroll 4
    for (int i = start + threadIdx.x; i < end; i += blockDim.x) {
        int bin = g_bins[i];
        unsigned int pos = s_base[bin] + atomicAdd(&s_cnt[bin], 1u);
        g_sorted_idx[pos] = (unsigned int)i;
    }
}

__device__ __forceinline__ float f4_sel(float4 q, int k)
{
    float lo = (k & 1) ? q.y : q.x;
    float hi = (k & 1) ? q.w : q.z;
    return (k & 2) ? hi : lo;
}

// Sample both x-texels of one row using an aligned float4 window.
__device__ __forceinline__ float row_lerp(
    const float4* __restrict__ row, int b4, int off, int a4, int ao, float wx)
{
    float4 q = __ldg(row + b4);
    float4 q2 = q;
    if (a4 != b4) q2 = __ldg(row + a4);
    float c0 = f4_sel(q, off);
    float c1 = f4_sel(q2, ao);
    return fmaf(wx, c1 - c0, c0);
}

__device__ __forceinline__ float trilerp_slice4(
    const float* __restrict__ f, int t,
    int z0, int z1, int y0, int y1,
    int b4, int off, int a4, int ao,
    float wz, float wy, float wx)
{
    const int tb = t * Z_DIM;
    const float4* r00 = (const float4*)f + ((long)((tb + z0) * Y_DIM + y0) << 8);
    const float4* r01 = (const float4*)f + ((long)((tb + z0) * Y_DIM + y1) << 8);
    const float4* r10 = (const float4*)f + ((long)((tb + z1) * Y_DIM + y0) << 8);
    const float4* r11 = (const float4*)f + ((long)((tb + z1) * Y_DIM + y1) << 8);

    float c00 = row_lerp(r00, b4, off, a4, ao, wx);
    float c01 = row_lerp(r01, b4, off, a4, ao, wx);
    float c10 = row_lerp(r10, b4, off, a4, ao, wx);
    float c11 = row_lerp(r11, b4, off, a4, ao, wx);

    float c0 = fmaf(wy, c01 - c00, c00);
    float c1 = fmaf(wy, c11 - c10, c10);
    return fmaf(wz, c1 - c0, c0);
}

__device__ __forceinline__ float sample_point(
    const float4 c, const float* __restrict__ frames)
{
    float t_abs = c.w * 3.0f;
    int t0 = min(max((int)t_abs, 0), 2);
    int t1 = min(t0 + 1, T_DIM - 1);
    float w = t_abs - (float)t0;

    float sz = c.x * (float)(Z_DIM - 1);
    float sy = c.y * (float)(Y_DIM - 1);
    float sx = c.z * (float)(X_DIM - 1);

    int iz = (int)sz;   // inputs in [0,1): trunc == floor
    int iy = (int)sy;
    int ix = (int)sx;

    float wz = sz - (float)iz;
    float wy = sy - (float)iy;
    float wx = sx - (float)ix;

    int z0 = max(0, min(iz, Z_DIM - 1));
    int y0 = max(0, min(iy, Y_DIM - 1));
    int x0 = max(0, min(ix, X_DIM - 1));
    int z1 = min(z0 + 1, Z_DIM - 1);
    int y1 = min(y0 + 1, Y_DIM - 1);
    int x1 = min(x0 + 1, X_DIM - 1);

    int b4 = x0 >> 2, off = x0 & 3;
    int a4 = x1 >> 2, ao  = x1 & 3;

    float val0 = trilerp_slice4(frames, t0, z0, z1, y0, y1, b4, off, a4, ao, wz, wy, wx);

    if (t1 != t0) {
        float val1 = trilerp_slice4(frames, t1, z0, z1, y0, y1, b4, off, a4, ao, wz, wy, wx);
        return fmaf(w, val1 - val0, val0);
    }
    return val0;
}

__global__ void __launch_bounds__(256)
sample_sorted_kernel(const float4* __restrict__ coords,
                     const float*  __restrict__ frames,
                     float*        __restrict__ out,
                     int n)
{
    int j = blockIdx.x * blockDim.x + threadIdx.x;
    if (j >= n) return;

    unsigned int i = __ldg(&g_sorted_idx[j]);
    float4 c = __ldg(&coords[i]);
    out[i] = sample_point(c, frames);
}

__global__ void __launch_bounds__(256)
sample_direct_kernel(const float4* __restrict__ coords,
                     const float*  __restrict__ frames,
                     float*        __restrict__ out,
                     int n)
{
    int i = blockIdx.x * blockDim.x + threadIdx.x;
    if (i >= n) return;
    float4 c = __ldg(&coords[i]);
    out[i] = sample_point(c, frames);
}

extern "C" void kernel_launch(void* const* d_in, const int* in_sizes, int n_in,
                              void* d_out, int out_size)
{
    const float4* coords = (const float4*)d_in[0];
    const float*  frames = (const float*)d_in[1];
    float* out = (float*)d_out;

    int n = in_sizes[0] / 4;   // coords is (N,4) floats
    int blocks = (n + 255) / 256;

    if (n > CAP) {
        sample_direct_kernel<<<blocks, 256>>>(coords, frames, out, n);
        return;
    }

    int chunk = (n + NCTA - 1) / NCTA;

    hist_kernel<<<NCTA, CHUNK_THREADS>>>(coords, n, chunk);
    scan1_kernel<<<NBINS, NCTA>>>();
    scan2_kernel<<<1, 1024>>>();
    scatter_kernel<<<NCTA, CHUNK_THREADS>>>(n, chunk);
    sample_sorted_kernel<<<blocks, 256>>>(coords, frames, out, n);
}

// round 12
// speedup vs baseline: 2.2499x; 1.0613x over previous
#include <cuda_runtime.h>

// ZapBench volume sampler: quadrilinear (trilinear spatial + linear temporal)
// frames: (T=3, Z=72, Y=512, X=1024) fp32, coords: (N, 4) fp32 [z, y, x, t]
// out: (N, 1) fp32
//
// R12: single-pass padded-bin sort. Each of 1728 bins (t innermost) owns a
// fixed 4096-slot region; one fused kernel computes bins (kept in smem),
// reserves per-CTA ranges with one global atomicAdd per touched bin, and
// places indices. Overflow (statistically ~never for uniform coords) goes to
// a side list handled by a direct-gather kernel — output is identical either
// way, so results stay deterministic. Replaces the 4-kernel 75us sort.

#define T_DIM 3
#define Z_DIM 72
#define Y_DIM 512
#define X_DIM 1024

#define NBINS (9 * 8 * 8 * 3)    // (z/8, y/64, x/128) spatial, t0 innermost
#define BIN_CAP 4096             // slots per bin (mean fill ~2427)
#define TILES (BIN_CAP / 256)    // 16 sample tiles per bin
#define CAP   (1 << 22)          // 4194304 points
#define CHUNK 8192               // points per fused-sort CTA
#define SORT_THREADS 512

__device__ unsigned int g_fill[NBINS];
__device__ unsigned int g_sorted_idx[NBINS * BIN_CAP];   // 28.3 MB
__device__ unsigned int g_ovf_cnt;
__device__ unsigned int g_ovf[CAP];                      // worst-case safe

__device__ __forceinline__ int compute_bin(float4 c)
{
    float t_abs = c.w * 3.0f;
    int t0 = min(max((int)t_abs, 0), 2);
    int zc = min(max((int)(c.x * (float)(Z_DIM - 1)), 0), Z_DIM - 1) >> 3;   // 0..8
    int yc = min(max((int)(c.y * (float)(Y_DIM - 1)), 0), Y_DIM - 1) >> 6;   // 0..7
    int xc = min(max((int)(c.z * (float)(X_DIM - 1)), 0), X_DIM - 1) >> 7;   // 0..7
    return (((zc * 8 + yc) * 8 + xc) * 3) + t0;   // t innermost
}

__global__ void zero_kernel()
{
    int i = blockIdx.x * blockDim.x + threadIdx.x;
    if (i < NBINS) g_fill[i] = 0;
    if (i == 0) g_ovf_cnt = 0;
}

// Fused sort: bin ids stay in smem; one global atomicAdd per (CTA, bin).
__global__ void __launch_bounds__(SORT_THREADS)
fused_sort_kernel(const float4* __restrict__ coords, int n)
{
    __shared__ unsigned short s_bin[CHUNK];
    __shared__ unsigned int   s_hist[NBINS];
    __shared__ unsigned int   s_base[NBINS];

    int start = blockIdx.x * CHUNK;
    int m = min(n - start, CHUNK);
    if (m <= 0) return;

    for (int b = threadIdx.x; b < NBINS; b += SORT_THREADS) s_hist[b] = 0;
    __syncthreads();

    #pragma unroll 4
    for (int k = threadIdx.x; k < m; k += SORT_THREADS) {
        float4 c = __ldg(&coords[start + k]);
        int bin = compute_bin(c);
        s_bin[k] = (unsigned short)bin;
        atomicAdd(&s_hist[bin], 1u);
    }
    __syncthreads();

    for (int b = threadIdx.x; b < NBINS; b += SORT_THREADS) {
        unsigned int cnt = s_hist[b];
        s_base[b] = cnt ? atomicAdd(&g_fill[b], cnt) : 0u;
        s_hist[b] = 0;
    }
    __syncthreads();

    #pragma unroll 4
    for (int k = threadIdx.x; k < m; k += SORT_THREADS) {
        int bin = s_bin[k];
        unsigned int off = s_base[bin] + atomicAdd(&s_hist[bin], 1u);
        unsigned int idx = (unsigned int)(start + k);
        if (off < BIN_CAP) {
            g_sorted_idx[(unsigned int)bin * BIN_CAP + off] = idx;
        } else {
            unsigned int p = atomicAdd(&g_ovf_cnt, 1u);
            g_ovf[p] = idx;   // p < CAP always (total points <= CAP)
        }
    }
}

__device__ __forceinline__ float f4_sel(float4 q, int k)
{
    float lo = (k & 1) ? q.y : q.x;
    float hi = (k & 1) ? q.w : q.z;
    return (k & 2) ? hi : lo;
}

// Sample both x-texels of one row using an aligned float4 window.
__device__ __forceinline__ float row_lerp(
    const float4* __restrict__ row, int b4, int off, int a4, int ao, float wx)
{
    float4 q = __ldg(row + b4);
    float4 q2 = q;
    if (a4 != b4) q2 = __ldg(row + a4);
    float c0 = f4_sel(q, off);
    float c1 = f4_sel(q2, ao);
    return fmaf(wx, c1 - c0, c0);
}

__device__ __forceinline__ float trilerp_slice4(
    const float* __restrict__ f, int t,
    int z0, int z1, int y0, int y1,
    int b4, int off, int a4, int ao,
    float wz, float wy, float wx)
{
    const int tb = t * Z_DIM;
    const float4* r00 = (const float4*)f + ((long)((tb + z0) * Y_DIM + y0) << 8);
    const float4* r01 = (const float4*)f + ((long)((tb + z0) * Y_DIM + y1) << 8);
    const float4* r10 = (const float4*)f + ((long)((tb + z1) * Y_DIM + y0) << 8);
    const float4* r11 = (const float4*)f + ((long)((tb + z1) * Y_DIM + y1) << 8);

    float c00 = row_lerp(r00, b4, off, a4, ao, wx);
    float c01 = row_lerp(r01, b4, off, a4, ao, wx);
    float c10 = row_lerp(r10, b4, off, a4, ao, wx);
    float c11 = row_lerp(r11, b4, off, a4, ao, wx);

    float c0 = fmaf(wy, c01 - c00, c00);
    float c1 = fmaf(wy, c11 - c10, c10);
    return fmaf(wz, c1 - c0, c0);
}

__device__ __forceinline__ float sample_point(
    const float4 c, const float* __restrict__ frames)
{
    float t_abs = c.w * 3.0f;
    int t0 = min(max((int)t_abs, 0), 2);
    int t1 = min(t0 + 1, T_DIM - 1);
    float w = t_abs - (float)t0;

    float sz = c.x * (float)(Z_DIM - 1);
    float sy = c.y * (float)(Y_DIM - 1);
    float sx = c.z * (float)(X_DIM - 1);

    int iz = (int)sz;   // inputs in [0,1): trunc == floor
    int iy = (int)sy;
    int ix = (int)sx;

    float wz = sz - (float)iz;
    float wy = sy - (float)iy;
    float wx = sx - (float)ix;

    int z0 = max(0, min(iz, Z_DIM - 1));
    int y0 = max(0, min(iy, Y_DIM - 1));
    int x0 = max(0, min(ix, X_DIM - 1));
    int z1 = min(z0 + 1, Z_DIM - 1);
    int y1 = min(y0 + 1, Y_DIM - 1);
    int x1 = min(x0 + 1, X_DIM - 1);

    int b4 = x0 >> 2, off = x0 & 3;
    int a4 = x1 >> 2, ao  = x1 & 3;

    float val0 = trilerp_slice4(frames, t0, z0, z1, y0, y1, b4, off, a4, ao, wz, wy, wx);

    if (t1 != t0) {
        float val1 = trilerp_slice4(frames, t1, z0, z1, y0, y1, b4, off, a4, ao, wz, wy, wx);
        return fmaf(w, val1 - val0, val0);
    }
    return val0;
}

// One CTA per (bin, tile); empty tiles exit after a single coalesced load.
__global__ void __launch_bounds__(256)
sample_tiles_kernel(const float4* __restrict__ coords,
                    const float*  __restrict__ frames,
                    float*        __restrict__ out)
{
    int bin  = blockIdx.x / TILES;
    int tile = blockIdx.x % TILES;

    unsigned int cnt = __ldg(&g_fill[bin]);
    if (cnt > BIN_CAP) cnt = BIN_CAP;

    unsigned int j = tile * 256 + threadIdx.x;
    if (j >= cnt) return;

    unsigned int i = __ldg(&g_sorted_idx[(unsigned int)bin * BIN_CAP + j]);
    float4 c = __ldg(&coords[i]);
    out[i] = sample_point(c, frames);
}

// Overflow cleanup: direct gather for points that missed their bin region.
__global__ void __launch_bounds__(256)
sample_overflow_kernel(const float4* __restrict__ coords,
                       const float*  __restrict__ frames,
                       float*        __restrict__ out)
{
    unsigned int cnt = g_ovf_cnt;
    if (cnt > (unsigned int)CAP) cnt = CAP;
    unsigned int stride = gridDim.x * blockDim.x;
    for (unsigned int k = blockIdx.x * blockDim.x + threadIdx.x; k < cnt; k += stride) {
        unsigned int i = g_ovf[k];
        float4 c = __ldg(&coords[i]);
        out[i] = sample_point(c, frames);
    }
}

__global__ void __launch_bounds__(256)
sample_direct_kernel(const float4* __restrict__ coords,
                     const float*  __restrict__ frames,
                     float*        __restrict__ out,
                     int n)
{
    int i = blockIdx.x * blockDim.x + threadIdx.x;
    if (i >= n) return;
    float4 c = __ldg(&coords[i]);
    out[i] = sample_point(c, frames);
}

extern "C" void kernel_launch(void* const* d_in, const int* in_sizes, int n_in,
                              void* d_out, int out_size)
{
    const float4* coords = (const float4*)d_in[0];
    const float*  frames = (const float*)d_in[1];
    float* out = (float*)d_out;

    int n = in_sizes[0] / 4;   // coords is (N,4) floats

    if (n > CAP) {
        int blocks = (n + 255) / 256;
        sample_direct_kernel<<<blocks, 256>>>(coords, frames, out, n);
        return;
    }

    int sort_blocks = (n + CHUNK - 1) / CHUNK;

    zero_kernel<<<(NBINS + 255) / 256, 256>>>();
    fused_sort_kernel<<<sort_blocks, SORT_THREADS>>>(coords, n);
    sample_tiles_kernel<<<NBINS * TILES, 256>>>(coords, frames, out);
    sample_overflow_kernel<<<64, 256>>>(coords, frames, out);
}

// round 13
// speedup vs baseline: 2.2762x; 1.0117x over previous
#include <cuda_runtime.h>

// ZapBench volume sampler: quadrilinear (trilinear spatial + linear temporal)
// frames: (T=3, Z=72, Y=512, X=1024) fp32, coords: (N, 4) fp32 [z, y, x, t]
// out: (N, 1) fp32
//
// R12: single-pass padded-bin sort (each of 1728 bins owns a 4096-slot
// region; one fused kernel bins + reserves + places; overflow -> side list).
// R13: CHUNK 8192->4096 — the fused sort was latency-bound at 512 CTAs;
// double the CTA count for the same work.

#define T_DIM 3
#define Z_DIM 72
#define Y_DIM 512
#define X_DIM 1024

#define NBINS (9 * 8 * 8 * 3)    // (z/8, y/64, x/128) spatial, t0 innermost
#define BIN_CAP 4096             // slots per bin (mean fill ~2427)
#define TILES (BIN_CAP / 256)    // 16 sample tiles per bin
#define CAP   (1 << 22)          // 4194304 points
#define CHUNK 4096               // points per fused-sort CTA
#define SORT_THREADS 512

__device__ unsigned int g_fill[NBINS];
__device__ unsigned int g_sorted_idx[NBINS * BIN_CAP];   // 28.3 MB
__device__ unsigned int g_ovf_cnt;
__device__ unsigned int g_ovf[CAP];                      // worst-case safe

__device__ __forceinline__ int compute_bin(float4 c)
{
    float t_abs = c.w * 3.0f;
    int t0 = min(max((int)t_abs, 0), 2);
    int zc = min(max((int)(c.x * (float)(Z_DIM - 1)), 0), Z_DIM - 1) >> 3;   // 0..8
    int yc = min(max((int)(c.y * (float)(Y_DIM - 1)), 0), Y_DIM - 1) >> 6;   // 0..7
    int xc = min(max((int)(c.z * (float)(X_DIM - 1)), 0), X_DIM - 1) >> 7;   // 0..7
    return (((zc * 8 + yc) * 8 + xc) * 3) + t0;   // t innermost
}

__global__ void zero_kernel()
{
    int i = blockIdx.x * blockDim.x + threadIdx.x;
    if (i < NBINS) g_fill[i] = 0;
    if (i == 0) g_ovf_cnt = 0;
}

// Fused sort: bin ids stay in smem; one global atomicAdd per (CTA, bin).
__global__ void __launch_bounds__(SORT_THREADS)
fused_sort_kernel(const float4* __restrict__ coords, int n)
{
    __shared__ unsigned short s_bin[CHUNK];
    __shared__ unsigned int   s_hist[NBINS];
    __shared__ unsigned int   s_base[NBINS];

    int start = blockIdx.x * CHUNK;
    int m = min(n - start, CHUNK);
    if (m <= 0) return;

    for (int b = threadIdx.x; b < NBINS; b += SORT_THREADS) s_hist[b] = 0;
    __syncthreads();

    #pragma unroll 4
    for (int k = threadIdx.x; k < m; k += SORT_THREADS) {
        float4 c = __ldg(&coords[start + k]);
        int bin = compute_bin(c);
        s_bin[k] = (unsigned short)bin;
        atomicAdd(&s_hist[bin], 1u);
    }
    __syncthreads();

    for (int b = threadIdx.x; b < NBINS; b += SORT_THREADS) {
        unsigned int cnt = s_hist[b];
        s_base[b] = cnt ? atomicAdd(&g_fill[b], cnt) : 0u;
        s_hist[b] = 0;
    }
    __syncthreads();

    #pragma unroll 4
    for (int k = threadIdx.x; k < m; k += SORT_THREADS) {
        int bin = s_bin[k];
        unsigned int off = s_base[bin] + atomicAdd(&s_hist[bin], 1u);
        unsigned int idx = (unsigned int)(start + k);
        if (off < BIN_CAP) {
            g_sorted_idx[(unsigned int)bin * BIN_CAP + off] = idx;
        } else {
            unsigned int p = atomicAdd(&g_ovf_cnt, 1u);
            g_ovf[p] = idx;   // p < CAP always (total points <= CAP)
        }
    }
}

__device__ __forceinline__ float f4_sel(float4 q, int k)
{
    float lo = (k & 1) ? q.y : q.x;
    float hi = (k & 1) ? q.w : q.z;
    return (k & 2) ? hi : lo;
}

// Sample both x-texels of one row using an aligned float4 window.
__device__ __forceinline__ float row_lerp(
    const float4* __restrict__ row, int b4, int off, int a4, int ao, float wx)
{
    float4 q = __ldg(row + b4);
    float4 q2 = q;
    if (a4 != b4) q2 = __ldg(row + a4);
    float c0 = f4_sel(q, off);
    float c1 = f4_sel(q2, ao);
    return fmaf(wx, c1 - c0, c0);
}

__device__ __forceinline__ float trilerp_slice4(
    const float* __restrict__ f, int t,
    int z0, int z1, int y0, int y1,
    int b4, int off, int a4, int ao,
    float wz, float wy, float wx)
{
    const int tb = t * Z_DIM;
    const float4* r00 = (const float4*)f + ((long)((tb + z0) * Y_DIM + y0) << 8);
    const float4* r01 = (const float4*)f + ((long)((tb + z0) * Y_DIM + y1) << 8);
    const float4* r10 = (const float4*)f + ((long)((tb + z1) * Y_DIM + y0) << 8);
    const float4* r11 = (const float4*)f + ((long)((tb + z1) * Y_DIM + y1) << 8);

    float c00 = row_lerp(r00, b4, off, a4, ao, wx);
    float c01 = row_lerp(r01, b4, off, a4, ao, wx);
    float c10 = row_lerp(r10, b4, off, a4, ao, wx);
    float c11 = row_lerp(r11, b4, off, a4, ao, wx);

    float c0 = fmaf(wy, c01 - c00, c00);
    float c1 = fmaf(wy, c11 - c10, c10);
    return fmaf(wz, c1 - c0, c0);
}

__device__ __forceinline__ float sample_point(
    const float4 c, const float* __restrict__ frames)
{
    float t_abs = c.w * 3.0f;
    int t0 = min(max((int)t_abs, 0), 2);
    int t1 = min(t0 + 1, T_DIM - 1);
    float w = t_abs - (float)t0;

    float sz = c.x * (float)(Z_DIM - 1);
    float sy = c.y * (float)(Y_DIM - 1);
    float sx = c.z * (float)(X_DIM - 1);

    int iz = (int)sz;   // inputs in [0,1): trunc == floor
    int iy = (int)sy;
    int ix = (int)sx;

    float wz = sz - (float)iz;
    float wy = sy - (float)iy;
    float wx = sx - (float)ix;

    int z0 = max(0, min(iz, Z_DIM - 1));
    int y0 = max(0, min(iy, Y_DIM - 1));
    int x0 = max(0, min(ix, X_DIM - 1));
    int z1 = min(z0 + 1, Z_DIM - 1);
    int y1 = min(y0 + 1, Y_DIM - 1);
    int x1 = min(x0 + 1, X_DIM - 1);

    int b4 = x0 >> 2, off = x0 & 3;
    int a4 = x1 >> 2, ao  = x1 & 3;

    float val0 = trilerp_slice4(frames, t0, z0, z1, y0, y1, b4, off, a4, ao, wz, wy, wx);

    if (t1 != t0) {
        float val1 = trilerp_slice4(frames, t1, z0, z1, y0, y1, b4, off, a4, ao, wz, wy, wx);
        return fmaf(w, val1 - val0, val0);
    }
    return val0;
}

// One CTA per (bin, tile); empty tiles exit after a single coalesced load.
__global__ void __launch_bounds__(256)
sample_tiles_kernel(const float4* __restrict__ coords,
                    const float*  __restrict__ frames,
                    float*        __restrict__ out)
{
    int bin  = blockIdx.x / TILES;
    int tile = blockIdx.x % TILES;

    unsigned int cnt = __ldg(&g_fill[bin]);
    if (cnt > BIN_CAP) cnt = BIN_CAP;

    unsigned int j = tile * 256 + threadIdx.x;
    if (j >= cnt) return;

    unsigned int i = __ldg(&g_sorted_idx[(unsigned int)bin * BIN_CAP + j]);
    float4 c = __ldg(&coords[i]);
    out[i] = sample_point(c, frames);
}

// Overflow cleanup: direct gather for points that missed their bin region.
__global__ void __launch_bounds__(256)
sample_overflow_kernel(const float4* __restrict__ coords,
                       const float*  __restrict__ frames,
                       float*        __restrict__ out)
{
    unsigned int cnt = g_ovf_cnt;
    if (cnt > (unsigned int)CAP) cnt = CAP;
    unsigned int stride = gridDim.x * blockDim.x;
    for (unsigned int k = blockIdx.x * blockDim.x + threadIdx.x; k < cnt; k += stride) {
        unsigned int i = g_ovf[k];
        float4 c = __ldg(&coords[i]);
        out[i] = sample_point(c, frames);
    }
}

__global__ void __launch_bounds__(256)
sample_direct_kernel(const float4* __restrict__ coords,
                     const float*  __restrict__ frames,
                     float*        __restrict__ out,
                     int n)
{
    int i = blockIdx.x * blockDim.x + threadIdx.x;
    if (i >= n) return;
    float4 c = __ldg(&coords[i]);
    out[i] = sample_point(c, frames);
}

extern "C" void kernel_launch(void* const* d_in, const int* in_sizes, int n_in,
                              void* d_out, int out_size)
{
    const float4* coords = (const float4*)d_in[0];
    const float*  frames = (const float*)d_in[1];
    float* out = (float*)d_out;

    int n = in_sizes[0] / 4;   // coords is (N,4) floats

    if (n > CAP) {
        int blocks = (n + 255) / 256;
        sample_direct_kernel<<<blocks, 256>>>(coords, frames, out, n);
        return;
    }

    int sort_blocks = (n + CHUNK - 1) / CHUNK;

    zero_kernel<<<(NBINS + 255) / 256, 256>>>();
    fused_sort_kernel<<<sort_blocks, SORT_THREADS>>>(coords, n);
    sample_tiles_kernel<<<NBINS * TILES, 256>>>(coords, frames, out);
    sample_overflow_kernel<<<64, 256>>>(coords, frames, out);
}